// round 1
// baseline (speedup 1.0000x reference)
#include <cuda_runtime.h>
#include <math.h>

#define T_TOK 2048
#define DIM   2048
#define NEXP  8
#define FDIM  1408
#define BM 64
#define BN 64
#define BK 16

// ---- device scratch (no allocations allowed) ----
__device__ int   g_cnt[NEXP];
__device__ int   g_tok[NEXP][T_TOK];
__device__ float g_wt [NEXP][T_TOK];
__device__ float g_h  [NEXP * T_TOK * FDIM];   // 92.3 MB, holds SiLU(xWg)*(xWu)*w per (expert,slot)

// ---------------------------------------------------------------------------
// zero output + reset per-launch state (must run every replay inside graph)
// ---------------------------------------------------------------------------
__global__ void zero_kernel(float* __restrict__ out, int n) {
    int i = blockIdx.x * blockDim.x + threadIdx.x;
    if (i < n) out[i] = 0.0f;
    if (blockIdx.x == 0 && threadIdx.x < NEXP) g_cnt[threadIdx.x] = 0;
}

// ---------------------------------------------------------------------------
// router: logits -> softmax -> top2 -> renormalize -> scatter to expert lists
// one block (128 threads) per token
// ---------------------------------------------------------------------------
__global__ void router_kernel(const float* __restrict__ x,
                              const float* __restrict__ gw) {
    int t   = blockIdx.x;
    int tid = threadIdx.x;

    float p[NEXP];
#pragma unroll
    for (int e = 0; e < NEXP; e++) p[e] = 0.0f;

    const float* xr = x + (size_t)t * DIM;
    for (int d = tid; d < DIM; d += 128) {
        float xv = xr[d];
#pragma unroll
        for (int e = 0; e < NEXP; e++) p[e] += xv * gw[e * DIM + d];
    }

    __shared__ float sm[NEXP][128];
#pragma unroll
    for (int e = 0; e < NEXP; e++) sm[e][tid] = p[e];
    __syncthreads();

    for (int s = 64; s > 0; s >>= 1) {
        if (tid < s) {
#pragma unroll
            for (int e = 0; e < NEXP; e++) sm[e][tid] += sm[e][tid + s];
        }
        __syncthreads();
    }

    if (tid == 0) {
        float lg[NEXP];
        float mx = -1e30f;
#pragma unroll
        for (int e = 0; e < NEXP; e++) { lg[e] = sm[e][0]; mx = fmaxf(mx, lg[e]); }
        float pr[NEXP];
#pragma unroll
        for (int e = 0; e < NEXP; e++) pr[e] = expf(lg[e] - mx);
        // top-2 on probs (ties -> lowest index, matching jax.lax.top_k)
        int e0 = 0;
#pragma unroll
        for (int e = 1; e < NEXP; e++) if (pr[e] > pr[e0]) e0 = e;
        int e1 = (e0 == 0) ? 1 : 0;
#pragma unroll
        for (int e = 0; e < NEXP; e++)
            if (e != e0 && pr[e] > pr[e1]) e1 = e;
        float denom = pr[e0] + pr[e1];
        float w0 = pr[e0] / denom;
        float w1 = pr[e1] / denom;
        int p0 = atomicAdd(&g_cnt[e0], 1);
        g_tok[e0][p0] = t; g_wt[e0][p0] = w0;
        int p1 = atomicAdd(&g_cnt[e1], 1);
        g_tok[e1][p1] = t; g_wt[e1][p1] = w1;
    }
}

// ---------------------------------------------------------------------------
// gate+up GEMM per expert on gathered rows:
//   h[slot, f] = SiLU(x[tok]·Wg[e])[f] * (x[tok]·Wu[e])[f] * combine_weight
// grid: (FDIM/BN, T_TOK/BM, NEXP), early-exit on tiles past cnt[e]
// ---------------------------------------------------------------------------
__global__ void __launch_bounds__(256)
gateup_kernel(const float* __restrict__ x,
              const float* __restrict__ wg,
              const float* __restrict__ wu) {
    int e   = blockIdx.z;
    int cnt = g_cnt[e];
    int m0  = blockIdx.y * BM;
    if (m0 >= cnt) return;
    int n0  = blockIdx.x * BN;

    __shared__ float As[BK][BM];
    __shared__ float Bg[BK][BN];
    __shared__ float Bu[BK][BN];
    __shared__ int   stok[BM];
    __shared__ float swt[BM];

    int tid = threadIdx.x;
    if (tid < BM) {
        int m = m0 + tid;
        stok[tid] = (m < cnt) ? g_tok[e][m] : 0;
        swt[tid]  = (m < cnt) ? g_wt[e][m]  : 0.0f;
    }
    __syncthreads();

    const float* wgE = wg + (size_t)e * DIM * FDIM;
    const float* wuE = wu + (size_t)e * DIM * FDIM;

    float cg[4][4] = {}, cu[4][4] = {};
    int ty = tid / 16, tx = tid % 16;

    // load indices
    int lm  = tid / 4;          // token row 0..63 (A load)
    int lk4 = (tid % 4) * 4;    // k quad        (A load)
    int lk  = tid / 16;         // k row 0..15   (B load)
    int ln4 = (tid % 16) * 4;   // n quad        (B load)

    for (int kb = 0; kb < DIM; kb += BK) {
        float4 av = *reinterpret_cast<const float4*>(x + (size_t)stok[lm] * DIM + kb + lk4);
        As[lk4 + 0][lm] = av.x; As[lk4 + 1][lm] = av.y;
        As[lk4 + 2][lm] = av.z; As[lk4 + 3][lm] = av.w;
        *reinterpret_cast<float4*>(&Bg[lk][ln4]) =
            *reinterpret_cast<const float4*>(wgE + (size_t)(kb + lk) * FDIM + n0 + ln4);
        *reinterpret_cast<float4*>(&Bu[lk][ln4]) =
            *reinterpret_cast<const float4*>(wuE + (size_t)(kb + lk) * FDIM + n0 + ln4);
        __syncthreads();

#pragma unroll
        for (int k = 0; k < BK; k++) {
            float a[4], bg[4], bu[4];
#pragma unroll
            for (int i = 0; i < 4; i++) a[i] = As[k][ty * 4 + i];
            float4 bgv = *reinterpret_cast<const float4*>(&Bg[k][tx * 4]);
            float4 buv = *reinterpret_cast<const float4*>(&Bu[k][tx * 4]);
            bg[0] = bgv.x; bg[1] = bgv.y; bg[2] = bgv.z; bg[3] = bgv.w;
            bu[0] = buv.x; bu[1] = buv.y; bu[2] = buv.z; bu[3] = buv.w;
#pragma unroll
            for (int i = 0; i < 4; i++)
#pragma unroll
                for (int j = 0; j < 4; j++) {
                    cg[i][j] += a[i] * bg[j];
                    cu[i][j] += a[i] * bu[j];
                }
        }
        __syncthreads();
    }

#pragma unroll
    for (int i = 0; i < 4; i++) {
        int m = m0 + ty * 4 + i;
        if (m >= cnt) continue;
        float w = swt[ty * 4 + i];
        float* hrow = g_h + ((size_t)e * T_TOK + m) * FDIM + n0 + tx * 4;
        float4 hv;
        float g0 = cg[i][0], g1 = cg[i][1], g2 = cg[i][2], g3 = cg[i][3];
        hv.x = (g0 / (1.0f + __expf(-g0))) * cu[i][0] * w;
        hv.y = (g1 / (1.0f + __expf(-g1))) * cu[i][1] * w;
        hv.z = (g2 / (1.0f + __expf(-g2))) * cu[i][2] * w;
        hv.w = (g3 / (1.0f + __expf(-g3))) * cu[i][3] * w;
        *reinterpret_cast<float4*>(hrow) = hv;
    }
}

// ---------------------------------------------------------------------------
// down GEMM per expert + scatter-add into output:
//   out[tok, d] += (h[slot] · Wd[e])[d]     (combine weight already in h)
// grid: (DIM/BN, T_TOK/BM, NEXP)
// ---------------------------------------------------------------------------
__global__ void __launch_bounds__(256)
down_kernel(const float* __restrict__ wd, float* __restrict__ out) {
    int e   = blockIdx.z;
    int cnt = g_cnt[e];
    int m0  = blockIdx.y * BM;
    if (m0 >= cnt) return;
    int n0  = blockIdx.x * BN;

    __shared__ float As[BK][BM];
    __shared__ float Bd[BK][BN];
    __shared__ int   stok[BM];

    int tid = threadIdx.x;
    if (tid < BM) {
        int m = m0 + tid;
        stok[tid] = (m < cnt) ? g_tok[e][m] : 0;
    }
    __syncthreads();

    const float* wdE = wd + (size_t)e * FDIM * DIM;
    const float* hE  = g_h + (size_t)e * T_TOK * FDIM;

    float c[4][4] = {};
    int ty = tid / 16, tx = tid % 16;

    int lm  = tid / 4;
    int lk4 = (tid % 4) * 4;
    int lk  = tid / 16;
    int ln4 = (tid % 16) * 4;

    for (int kb = 0; kb < FDIM; kb += BK) {
        float4 av = *reinterpret_cast<const float4*>(hE + (size_t)(m0 + lm) * FDIM + kb + lk4);
        As[lk4 + 0][lm] = av.x; As[lk4 + 1][lm] = av.y;
        As[lk4 + 2][lm] = av.z; As[lk4 + 3][lm] = av.w;
        *reinterpret_cast<float4*>(&Bd[lk][ln4]) =
            *reinterpret_cast<const float4*>(wdE + (size_t)(kb + lk) * DIM + n0 + ln4);
        __syncthreads();

#pragma unroll
        for (int k = 0; k < BK; k++) {
            float a[4], b[4];
#pragma unroll
            for (int i = 0; i < 4; i++) a[i] = As[k][ty * 4 + i];
            float4 bv = *reinterpret_cast<const float4*>(&Bd[k][tx * 4]);
            b[0] = bv.x; b[1] = bv.y; b[2] = bv.z; b[3] = bv.w;
#pragma unroll
            for (int i = 0; i < 4; i++)
#pragma unroll
                for (int j = 0; j < 4; j++) c[i][j] += a[i] * b[j];
        }
        __syncthreads();
    }

#pragma unroll
    for (int i = 0; i < 4; i++) {
        int m = m0 + ty * 4 + i;
        if (m >= cnt) continue;
        int tok = stok[ty * 4 + i];
        float* orow = out + (size_t)tok * DIM + n0 + tx * 4;
#pragma unroll
        for (int j = 0; j < 4; j++) atomicAdd(&orow[j], c[i][j]);
    }
}

// ---------------------------------------------------------------------------
extern "C" void kernel_launch(void* const* d_in, const int* in_sizes, int n_in,
                              void* d_out, int out_size) {
    const float* x  = (const float*)d_in[0];   // [B,S,D] = [T, D]
    const float* gw = (const float*)d_in[1];   // [E, D]
    const float* wg = (const float*)d_in[2];   // [E, D, F]
    const float* wu = (const float*)d_in[3];   // [E, D, F]
    const float* wd = (const float*)d_in[4];   // [E, F, D]
    float* out = (float*)d_out;                // [T, D]

    int n_out = T_TOK * DIM;
    zero_kernel<<<(n_out + 255) / 256, 256>>>(out, n_out);
    router_kernel<<<T_TOK, 128>>>(x, gw);

    dim3 g2(FDIM / BN, T_TOK / BM, NEXP);
    gateup_kernel<<<g2, 256>>>(x, wg, wu);

    dim3 g3(DIM / BN, T_TOK / BM, NEXP);
    down_kernel<<<g3, 256>>>(wd, out);
}

// round 2
// speedup vs baseline: 2.2085x; 2.2085x over previous
#include <cuda_runtime.h>
#include <math.h>

#define T_TOK 2048
#define DIM   2048
#define NEXP  8
#define FDIM  1408

// ---- device scratch (no allocations allowed) ----
__device__ int   g_cnt[NEXP];
__device__ int   g_tok[NEXP][T_TOK];
__device__ float g_wt [NEXP][T_TOK];
__device__ float g_h  [NEXP * T_TOK * FDIM];   // SiLU(xWg)*(xWu)*w per (expert,slot); unwritten rows stay 0

// ---------------------------------------------------------------------------
__device__ __forceinline__ unsigned f2tf32(float x) {
    unsigned r; asm("cvt.rna.tf32.f32 %0, %1;" : "=r"(r) : "f"(x)); return r;
}
__device__ __forceinline__ void mma_tf32(float* c, const unsigned* a, const unsigned* b) {
    asm volatile(
        "mma.sync.aligned.m16n8k8.row.col.f32.tf32.tf32.f32 "
        "{%0,%1,%2,%3}, {%4,%5,%6,%7}, {%8,%9}, {%0,%1,%2,%3};\n"
        : "+f"(c[0]), "+f"(c[1]), "+f"(c[2]), "+f"(c[3])
        : "r"(a[0]), "r"(a[1]), "r"(a[2]), "r"(a[3]), "r"(b[0]), "r"(b[1]));
}

// ---------------------------------------------------------------------------
__global__ void zero_kernel(float* __restrict__ out, int n) {
    int i = blockIdx.x * blockDim.x + threadIdx.x;
    if (i < n) out[i] = 0.0f;
    if (blockIdx.x == 0 && threadIdx.x < NEXP) g_cnt[threadIdx.x] = 0;
}

// ---------------------------------------------------------------------------
// router: logits -> softmax -> top2 -> renorm -> scatter to expert lists
// ---------------------------------------------------------------------------
__global__ void router_kernel(const float* __restrict__ x,
                              const float* __restrict__ gw) {
    int t   = blockIdx.x;
    int tid = threadIdx.x;

    float p[NEXP];
#pragma unroll
    for (int e = 0; e < NEXP; e++) p[e] = 0.0f;

    const float* xr = x + (size_t)t * DIM;
    for (int d = tid; d < DIM; d += 128) {
        float xv = xr[d];
#pragma unroll
        for (int e = 0; e < NEXP; e++) p[e] += xv * gw[e * DIM + d];
    }

    __shared__ float sm[NEXP][128];
#pragma unroll
    for (int e = 0; e < NEXP; e++) sm[e][tid] = p[e];
    __syncthreads();

    for (int s = 64; s > 0; s >>= 1) {
        if (tid < s) {
#pragma unroll
            for (int e = 0; e < NEXP; e++) sm[e][tid] += sm[e][tid + s];
        }
        __syncthreads();
    }

    if (tid == 0) {
        float lg[NEXP];
        float mx = -1e30f;
#pragma unroll
        for (int e = 0; e < NEXP; e++) { lg[e] = sm[e][0]; mx = fmaxf(mx, lg[e]); }
        float pr[NEXP];
#pragma unroll
        for (int e = 0; e < NEXP; e++) pr[e] = expf(lg[e] - mx);
        int e0 = 0;
#pragma unroll
        for (int e = 1; e < NEXP; e++) if (pr[e] > pr[e0]) e0 = e;
        int e1 = (e0 == 0) ? 1 : 0;
#pragma unroll
        for (int e = 0; e < NEXP; e++)
            if (e != e0 && pr[e] > pr[e1]) e1 = e;
        float denom = pr[e0] + pr[e1];
        float w0 = pr[e0] / denom;
        float w1 = pr[e1] / denom;
        int p0 = atomicAdd(&g_cnt[e0], 1);
        g_tok[e0][p0] = t; g_wt[e0][p0] = w0;
        int p1 = atomicAdd(&g_cnt[e1], 1);
        g_tok[e1][p1] = t; g_wt[e1][p1] = w1;
    }
}

// ---------------------------------------------------------------------------
// gate+up tensor-core GEMM (tf32 mma.sync), tile 128x64x32, 8 warps (4M x 2N)
//   h[slot, f] = SiLU(x Wg)[f] * (x Wu)[f] * combine_weight
// ---------------------------------------------------------------------------
#define BM 128
#define BN 64
#define BK 32
#define APAD 8
#define BPAD 8

__global__ void __launch_bounds__(256, 2)
gateup_mma(const float* __restrict__ x,
           const float* __restrict__ wg,
           const float* __restrict__ wu) {
    int e   = blockIdx.z;
    int cnt = g_cnt[e];
    int m0  = blockIdx.y * BM;
    if (m0 >= cnt) return;
    int n0  = blockIdx.x * BN;

    __shared__ unsigned As[BK][BM + APAD];
    __shared__ unsigned Bg[BK][BN + BPAD];
    __shared__ unsigned Bu[BK][BN + BPAD];
    __shared__ int   stok[BM];
    __shared__ float swt[BM];

    int tid = threadIdx.x;
    if (tid < BM) {
        int m = m0 + tid;
        stok[tid] = (m < cnt) ? g_tok[e][m] : 0;
        swt[tid]  = (m < cnt) ? g_wt[e][m]  : 0.0f;
    }
    __syncthreads();

    const float* wgE = wg + (size_t)e * DIM * FDIM;
    const float* wuE = wu + (size_t)e * DIM * FDIM;

    int wid  = tid >> 5, lane = tid & 31;
    int gid  = lane >> 2, tig = lane & 3;
    int warpM = wid & 3, warpN = wid >> 2;       // 4 x 2 warp grid
    int wm = warpM * 32, wn = warpN * 32;

    float cg[2][4][4] = {}, cu[2][4][4] = {};

    int arow  = tid >> 1;          // 0..127
    int ahalf = (tid & 1) * 16;    // k sub-base within BK
    int bbase = tid * 2;           // float4 id base for B tiles

    for (int kb = 0; kb < DIM; kb += BK) {
        // A: gathered token rows, fp32 -> tf32 into k-major smem
        const float* xr = x + (size_t)stok[arow] * DIM + kb + ahalf;
#pragma unroll
        for (int q = 0; q < 4; q++) {
            float4 v = *reinterpret_cast<const float4*>(xr + q * 4);
            As[ahalf + q * 4 + 0][arow] = f2tf32(v.x);
            As[ahalf + q * 4 + 1][arow] = f2tf32(v.y);
            As[ahalf + q * 4 + 2][arow] = f2tf32(v.z);
            As[ahalf + q * 4 + 3][arow] = f2tf32(v.w);
        }
        // B tiles (gate, up)
#pragma unroll
        for (int q = 0; q < 2; q++) {
            int f  = bbase + q;
            int k  = f >> 4;
            int nn = (f & 15) * 4;
            float4 vg = *reinterpret_cast<const float4*>(wgE + (size_t)(kb + k) * FDIM + n0 + nn);
            float4 vu = *reinterpret_cast<const float4*>(wuE + (size_t)(kb + k) * FDIM + n0 + nn);
            Bg[k][nn + 0] = f2tf32(vg.x); Bg[k][nn + 1] = f2tf32(vg.y);
            Bg[k][nn + 2] = f2tf32(vg.z); Bg[k][nn + 3] = f2tf32(vg.w);
            Bu[k][nn + 0] = f2tf32(vu.x); Bu[k][nn + 1] = f2tf32(vu.y);
            Bu[k][nn + 2] = f2tf32(vu.z); Bu[k][nn + 3] = f2tf32(vu.w);
        }
        __syncthreads();

#pragma unroll
        for (int ks = 0; ks < BK / 8; ks++) {
            unsigned a[2][4];
#pragma unroll
            for (int mi = 0; mi < 2; mi++) {
                int r = wm + mi * 16;
                a[mi][0] = As[ks * 8 + tig    ][r + gid    ];
                a[mi][1] = As[ks * 8 + tig    ][r + gid + 8];
                a[mi][2] = As[ks * 8 + tig + 4][r + gid    ];
                a[mi][3] = As[ks * 8 + tig + 4][r + gid + 8];
            }
#pragma unroll
            for (int ni = 0; ni < 4; ni++) {
                int nc = wn + ni * 8 + gid;
                unsigned bg[2] = { Bg[ks * 8 + tig][nc], Bg[ks * 8 + tig + 4][nc] };
                unsigned bu[2] = { Bu[ks * 8 + tig][nc], Bu[ks * 8 + tig + 4][nc] };
#pragma unroll
                for (int mi = 0; mi < 2; mi++) {
                    mma_tf32(cg[mi][ni], a[mi], bg);
                    mma_tf32(cu[mi][ni], a[mi], bu);
                }
            }
        }
        __syncthreads();
    }

    // epilogue: SiLU(g)*u*w -> g_h
#pragma unroll
    for (int mi = 0; mi < 2; mi++) {
#pragma unroll
        for (int half = 0; half < 2; half++) {
            int lm = wm + mi * 16 + gid + half * 8;
            int m  = m0 + lm;
            if (m >= cnt) continue;
            float w = swt[lm];
            float* hrow = g_h + ((size_t)e * T_TOK + m) * FDIM + n0;
#pragma unroll
            for (int ni = 0; ni < 4; ni++) {
                int col = wn + ni * 8 + 2 * tig;
                float g0 = cg[mi][ni][half * 2 + 0], g1 = cg[mi][ni][half * 2 + 1];
                float u0 = cu[mi][ni][half * 2 + 0], u1 = cu[mi][ni][half * 2 + 1];
                float2 hv;
                hv.x = (g0 / (1.0f + __expf(-g0))) * u0 * w;
                hv.y = (g1 / (1.0f + __expf(-g1))) * u1 * w;
                *reinterpret_cast<float2*>(hrow + col) = hv;
            }
        }
    }
}

// ---------------------------------------------------------------------------
// down tensor-core GEMM + scatter-add, tile 128x64x32
//   out[tok, d] += (h[slot] · Wd[e])[d]
// ---------------------------------------------------------------------------
__global__ void __launch_bounds__(256, 2)
down_mma(const float* __restrict__ wd, float* __restrict__ out) {
    int e   = blockIdx.z;
    int cnt = g_cnt[e];
    int m0  = blockIdx.y * BM;
    if (m0 >= cnt) return;
    int n0  = blockIdx.x * BN;

    __shared__ unsigned As[BK][BM + APAD];
    __shared__ unsigned Bd[BK][BN + BPAD];
    __shared__ int stok[BM];

    int tid = threadIdx.x;
    if (tid < BM) {
        int m = m0 + tid;
        stok[tid] = (m < cnt) ? g_tok[e][m] : 0;
    }
    __syncthreads();

    const float* wdE = wd + (size_t)e * FDIM * DIM;
    const float* hE  = g_h + (size_t)e * T_TOK * FDIM;

    int wid  = tid >> 5, lane = tid & 31;
    int gid  = lane >> 2, tig = lane & 3;
    int warpM = wid & 3, warpN = wid >> 2;
    int wm = warpM * 32, wn = warpN * 32;

    float c[2][4][4] = {};

    int arow  = tid >> 1;
    int ahalf = (tid & 1) * 16;
    int bbase = tid;               // 512 float4 in B tile / 256 thr = 2 each, strided

    for (int kb = 0; kb < FDIM; kb += BK) {
        const float* hr = hE + (size_t)(m0 + arow) * FDIM + kb + ahalf;
#pragma unroll
        for (int q = 0; q < 4; q++) {
            float4 v = *reinterpret_cast<const float4*>(hr + q * 4);
            As[ahalf + q * 4 + 0][arow] = f2tf32(v.x);
            As[ahalf + q * 4 + 1][arow] = f2tf32(v.y);
            As[ahalf + q * 4 + 2][arow] = f2tf32(v.z);
            As[ahalf + q * 4 + 3][arow] = f2tf32(v.w);
        }
#pragma unroll
        for (int q = 0; q < 2; q++) {
            int f  = bbase + q * 256;
            int k  = f >> 4;
            int nn = (f & 15) * 4;
            float4 vd = *reinterpret_cast<const float4*>(wdE + (size_t)(kb + k) * DIM + n0 + nn);
            Bd[k][nn + 0] = f2tf32(vd.x); Bd[k][nn + 1] = f2tf32(vd.y);
            Bd[k][nn + 2] = f2tf32(vd.z); Bd[k][nn + 3] = f2tf32(vd.w);
        }
        __syncthreads();

#pragma unroll
        for (int ks = 0; ks < BK / 8; ks++) {
            unsigned a[2][4];
#pragma unroll
            for (int mi = 0; mi < 2; mi++) {
                int r = wm + mi * 16;
                a[mi][0] = As[ks * 8 + tig    ][r + gid    ];
                a[mi][1] = As[ks * 8 + tig    ][r + gid + 8];
                a[mi][2] = As[ks * 8 + tig + 4][r + gid    ];
                a[mi][3] = As[ks * 8 + tig + 4][r + gid + 8];
            }
#pragma unroll
            for (int ni = 0; ni < 4; ni++) {
                int nc = wn + ni * 8 + gid;
                unsigned b[2] = { Bd[ks * 8 + tig][nc], Bd[ks * 8 + tig + 4][nc] };
#pragma unroll
                for (int mi = 0; mi < 2; mi++) {
                    mma_tf32(c[mi][ni], a[mi], b);
                }
            }
        }
        __syncthreads();
    }

    // epilogue: atomicAdd scatter (each out element gets exactly 2 adds total -> deterministic)
#pragma unroll
    for (int mi = 0; mi < 2; mi++) {
#pragma unroll
        for (int half = 0; half < 2; half++) {
            int lm = wm + mi * 16 + gid + half * 8;
            int m  = m0 + lm;
            if (m >= cnt) continue;
            int tok = stok[lm];
            float* orow = out + (size_t)tok * DIM + n0;
#pragma unroll
            for (int ni = 0; ni < 4; ni++) {
                int col = wn + ni * 8 + 2 * tig;
                atomicAdd(&orow[col + 0], c[mi][ni][half * 2 + 0]);
                atomicAdd(&orow[col + 1], c[mi][ni][half * 2 + 1]);
            }
        }
    }
}

// ---------------------------------------------------------------------------
extern "C" void kernel_launch(void* const* d_in, const int* in_sizes, int n_in,
                              void* d_out, int out_size) {
    const float* x  = (const float*)d_in[0];   // [T, D]
    const float* gw = (const float*)d_in[1];   // [E, D]
    const float* wg = (const float*)d_in[2];   // [E, D, F]
    const float* wu = (const float*)d_in[3];   // [E, D, F]
    const float* wd = (const float*)d_in[4];   // [E, F, D]
    float* out = (float*)d_out;

    int n_out = T_TOK * DIM;
    zero_kernel<<<(n_out + 255) / 256, 256>>>(out, n_out);
    router_kernel<<<T_TOK, 128>>>(x, gw);

    dim3 g2(FDIM / BN, T_TOK / BM, NEXP);      // (22, 16, 8)
    gateup_mma<<<g2, 256>>>(x, wg, wu);

    dim3 g3(DIM / BN, T_TOK / BM, NEXP);       // (32, 16, 8)
    down_mma<<<g3, 256>>>(wd, out);
}

// round 3
// speedup vs baseline: 2.2392x; 1.0139x over previous
#include <cuda_runtime.h>
#include <math.h>

#define T_TOK 2048
#define DIM   2048
#define NEXP  8
#define FDIM  1408

// ---- device scratch (no allocations allowed) ----
__device__ int   g_cnt[NEXP];
__device__ int   g_tok[NEXP][T_TOK];
__device__ float g_wt [NEXP][T_TOK];
__device__ float g_h  [NEXP * T_TOK * FDIM];   // SiLU(xWg)*(xWu)*w; unwritten rows stay 0

// ---------------------------------------------------------------------------
__device__ __forceinline__ unsigned f2tf32(float x) {
    unsigned r; asm("cvt.rna.tf32.f32 %0, %1;" : "=r"(r) : "f"(x)); return r;
}
__device__ __forceinline__ void mma_tf32(float* c, const unsigned* a, const unsigned* b) {
    asm volatile(
        "mma.sync.aligned.m16n8k8.row.col.f32.tf32.tf32.f32 "
        "{%0,%1,%2,%3}, {%4,%5,%6,%7}, {%8,%9}, {%0,%1,%2,%3};\n"
        : "+f"(c[0]), "+f"(c[1]), "+f"(c[2]), "+f"(c[3])
        : "r"(a[0]), "r"(a[1]), "r"(a[2]), "r"(a[3]), "r"(b[0]), "r"(b[1]));
}

// ---------------------------------------------------------------------------
__global__ void zero_kernel(float* __restrict__ out, int n) {
    int i = blockIdx.x * blockDim.x + threadIdx.x;
    if (i < n) out[i] = 0.0f;
    if (blockIdx.x == 0 && threadIdx.x < NEXP) g_cnt[threadIdx.x] = 0;
}

// ---------------------------------------------------------------------------
// router: logits -> softmax -> top2 -> renorm -> scatter to expert lists
// ---------------------------------------------------------------------------
__global__ void router_kernel(const float* __restrict__ x,
                              const float* __restrict__ gw) {
    int t   = blockIdx.x;
    int tid = threadIdx.x;

    float p[NEXP];
#pragma unroll
    for (int e = 0; e < NEXP; e++) p[e] = 0.0f;

    const float* xr = x + (size_t)t * DIM;
    for (int d = tid; d < DIM; d += 128) {
        float xv = xr[d];
#pragma unroll
        for (int e = 0; e < NEXP; e++) p[e] += xv * gw[e * DIM + d];
    }

    __shared__ float sm[NEXP][128];
#pragma unroll
    for (int e = 0; e < NEXP; e++) sm[e][tid] = p[e];
    __syncthreads();

    for (int s = 64; s > 0; s >>= 1) {
        if (tid < s) {
#pragma unroll
            for (int e = 0; e < NEXP; e++) sm[e][tid] += sm[e][tid + s];
        }
        __syncthreads();
    }

    if (tid == 0) {
        float lg[NEXP];
        float mx = -1e30f;
#pragma unroll
        for (int e = 0; e < NEXP; e++) { lg[e] = sm[e][0]; mx = fmaxf(mx, lg[e]); }
        float pr[NEXP];
#pragma unroll
        for (int e = 0; e < NEXP; e++) pr[e] = expf(lg[e] - mx);
        int e0 = 0;
#pragma unroll
        for (int e = 1; e < NEXP; e++) if (pr[e] > pr[e0]) e0 = e;
        int e1 = (e0 == 0) ? 1 : 0;
#pragma unroll
        for (int e = 0; e < NEXP; e++)
            if (e != e0 && pr[e] > pr[e1]) e1 = e;
        float denom = pr[e0] + pr[e1];
        float w0 = pr[e0] / denom;
        float w1 = pr[e1] / denom;
        int p0 = atomicAdd(&g_cnt[e0], 1);
        g_tok[e0][p0] = t; g_wt[e0][p0] = w0;
        int p1 = atomicAdd(&g_cnt[e1], 1);
        g_tok[e1][p1] = t; g_wt[e1][p1] = w1;
    }
}

// ---------------------------------------------------------------------------
#define BM 128
#define BN 64
#define BK 32
#define APAD 8
#define BPAD 8

// ---------------------------------------------------------------------------
// gate+up tensor-core GEMM, register-pipelined (prefetch next K-tile during MMA)
// ---------------------------------------------------------------------------
__global__ void __launch_bounds__(256, 2)
gateup_mma(const float* __restrict__ x,
           const float* __restrict__ wg,
           const float* __restrict__ wu) {
    int e   = blockIdx.z;
    int cnt = g_cnt[e];
    int m0  = blockIdx.y * BM;
    if (m0 >= cnt) return;
    int n0  = blockIdx.x * BN;

    __shared__ unsigned As[BK][BM + APAD];
    __shared__ unsigned Bg[BK][BN + BPAD];
    __shared__ unsigned Bu[BK][BN + BPAD];
    __shared__ int   stok[BM];
    __shared__ float swt[BM];

    int tid = threadIdx.x;
    if (tid < BM) {
        int m = m0 + tid;
        stok[tid] = (m < cnt) ? g_tok[e][m] : 0;
        swt[tid]  = (m < cnt) ? g_wt[e][m]  : 0.0f;
    }
    __syncthreads();

    const float* wgE = wg + (size_t)e * DIM * FDIM;
    const float* wuE = wu + (size_t)e * DIM * FDIM;

    int wid  = tid >> 5, lane = tid & 31;
    int gid  = lane >> 2, tig = lane & 3;
    int warpM = wid & 3, warpN = wid >> 2;       // 4 x 2 warp grid
    int wm = warpM * 32, wn = warpN * 32;

    float cg[2][4][4] = {}, cu[2][4][4] = {};

    int arow  = tid >> 1;          // 0..127
    int ahalf = (tid & 1) * 16;    // k sub-base within BK
    int bbase = tid * 2;           // float4 id base for B tiles
    int bk0 = bbase >> 4, bn0v = ((bbase    ) & 15) * 4;
    int bk1 = (bbase + 1) >> 4, bn1v = ((bbase + 1) & 15) * 4;

    const float* xr0 = x + (size_t)stok[arow] * DIM + ahalf;

    float4 av[4], vg[2], vu[2];
    // prologue: load tile kb=0
#pragma unroll
    for (int q = 0; q < 4; q++) av[q] = *reinterpret_cast<const float4*>(xr0 + q * 4);
    vg[0] = *reinterpret_cast<const float4*>(wgE + (size_t)bk0 * FDIM + n0 + bn0v);
    vg[1] = *reinterpret_cast<const float4*>(wgE + (size_t)bk1 * FDIM + n0 + bn1v);
    vu[0] = *reinterpret_cast<const float4*>(wuE + (size_t)bk0 * FDIM + n0 + bn0v);
    vu[1] = *reinterpret_cast<const float4*>(wuE + (size_t)bk1 * FDIM + n0 + bn1v);

    for (int kb = 0; kb < DIM; kb += BK) {
        // store current tile (regs -> smem, cvt to tf32)
#pragma unroll
        for (int q = 0; q < 4; q++) {
            As[ahalf + q * 4 + 0][arow] = f2tf32(av[q].x);
            As[ahalf + q * 4 + 1][arow] = f2tf32(av[q].y);
            As[ahalf + q * 4 + 2][arow] = f2tf32(av[q].z);
            As[ahalf + q * 4 + 3][arow] = f2tf32(av[q].w);
        }
        Bg[bk0][bn0v + 0] = f2tf32(vg[0].x); Bg[bk0][bn0v + 1] = f2tf32(vg[0].y);
        Bg[bk0][bn0v + 2] = f2tf32(vg[0].z); Bg[bk0][bn0v + 3] = f2tf32(vg[0].w);
        Bg[bk1][bn1v + 0] = f2tf32(vg[1].x); Bg[bk1][bn1v + 1] = f2tf32(vg[1].y);
        Bg[bk1][bn1v + 2] = f2tf32(vg[1].z); Bg[bk1][bn1v + 3] = f2tf32(vg[1].w);
        Bu[bk0][bn0v + 0] = f2tf32(vu[0].x); Bu[bk0][bn0v + 1] = f2tf32(vu[0].y);
        Bu[bk0][bn0v + 2] = f2tf32(vu[0].z); Bu[bk0][bn0v + 3] = f2tf32(vu[0].w);
        Bu[bk1][bn1v + 0] = f2tf32(vu[1].x); Bu[bk1][bn1v + 1] = f2tf32(vu[1].y);
        Bu[bk1][bn1v + 2] = f2tf32(vu[1].z); Bu[bk1][bn1v + 3] = f2tf32(vu[1].w);
        __syncthreads();

        // prefetch next tile into registers (overlaps with MMA below)
        int kn = kb + BK;
        if (kn < DIM) {
#pragma unroll
            for (int q = 0; q < 4; q++)
                av[q] = *reinterpret_cast<const float4*>(xr0 + kn + q * 4);
            vg[0] = *reinterpret_cast<const float4*>(wgE + (size_t)(kn + bk0) * FDIM + n0 + bn0v);
            vg[1] = *reinterpret_cast<const float4*>(wgE + (size_t)(kn + bk1) * FDIM + n0 + bn1v);
            vu[0] = *reinterpret_cast<const float4*>(wuE + (size_t)(kn + bk0) * FDIM + n0 + bn0v);
            vu[1] = *reinterpret_cast<const float4*>(wuE + (size_t)(kn + bk1) * FDIM + n0 + bn1v);
        }

#pragma unroll
        for (int ks = 0; ks < BK / 8; ks++) {
            unsigned a[2][4];
#pragma unroll
            for (int mi = 0; mi < 2; mi++) {
                int r = wm + mi * 16;
                a[mi][0] = As[ks * 8 + tig    ][r + gid    ];
                a[mi][1] = As[ks * 8 + tig    ][r + gid + 8];
                a[mi][2] = As[ks * 8 + tig + 4][r + gid    ];
                a[mi][3] = As[ks * 8 + tig + 4][r + gid + 8];
            }
#pragma unroll
            for (int ni = 0; ni < 4; ni++) {
                int nc = wn + ni * 8 + gid;
                unsigned bgf[2] = { Bg[ks * 8 + tig][nc], Bg[ks * 8 + tig + 4][nc] };
                unsigned buf[2] = { Bu[ks * 8 + tig][nc], Bu[ks * 8 + tig + 4][nc] };
#pragma unroll
                for (int mi = 0; mi < 2; mi++) {
                    mma_tf32(cg[mi][ni], a[mi], bgf);
                    mma_tf32(cu[mi][ni], a[mi], buf);
                }
            }
        }
        __syncthreads();
    }

    // epilogue: SiLU(g)*u*w -> g_h
#pragma unroll
    for (int mi = 0; mi < 2; mi++) {
#pragma unroll
        for (int half = 0; half < 2; half++) {
            int lm = wm + mi * 16 + gid + half * 8;
            int m  = m0 + lm;
            if (m >= cnt) continue;
            float w = swt[lm];
            float* hrow = g_h + ((size_t)e * T_TOK + m) * FDIM + n0;
#pragma unroll
            for (int ni = 0; ni < 4; ni++) {
                int col = wn + ni * 8 + 2 * tig;
                float g0 = cg[mi][ni][half * 2 + 0], g1 = cg[mi][ni][half * 2 + 1];
                float u0 = cu[mi][ni][half * 2 + 0], u1 = cu[mi][ni][half * 2 + 1];
                float2 hv;
                hv.x = (g0 / (1.0f + __expf(-g0))) * u0 * w;
                hv.y = (g1 / (1.0f + __expf(-g1))) * u1 * w;
                *reinterpret_cast<float2*>(hrow + col) = hv;
            }
        }
    }
}

// ---------------------------------------------------------------------------
// down tensor-core GEMM + scatter-add, register-pipelined
// ---------------------------------------------------------------------------
__global__ void __launch_bounds__(256, 2)
down_mma(const float* __restrict__ wd, float* __restrict__ out) {
    int e   = blockIdx.z;
    int cnt = g_cnt[e];
    int m0  = blockIdx.y * BM;
    if (m0 >= cnt) return;
    int n0  = blockIdx.x * BN;

    __shared__ unsigned As[BK][BM + APAD];
    __shared__ unsigned Bd[BK][BN + BPAD];
    __shared__ int stok[BM];

    int tid = threadIdx.x;
    if (tid < BM) {
        int m = m0 + tid;
        stok[tid] = (m < cnt) ? g_tok[e][m] : 0;
    }
    __syncthreads();

    const float* wdE = wd + (size_t)e * FDIM * DIM;
    const float* hE  = g_h + (size_t)e * T_TOK * FDIM;

    int wid  = tid >> 5, lane = tid & 31;
    int gid  = lane >> 2, tig = lane & 3;
    int warpM = wid & 3, warpN = wid >> 2;
    int wm = warpM * 32, wn = warpN * 32;

    float c[2][4][4] = {};

    int arow  = tid >> 1;
    int ahalf = (tid & 1) * 16;
    int bbase = tid;               // 512 float4 in B tile / 256 thr, stride 256
    int bk0 = bbase >> 4,        bn0v = (bbase & 15) * 4;
    int bk1 = (bbase + 256) >> 4, bn1v = ((bbase + 256) & 15) * 4;

    const float* hr0 = hE + (size_t)(m0 + arow) * FDIM + ahalf;

    float4 av[4], vd[2];
#pragma unroll
    for (int q = 0; q < 4; q++) av[q] = *reinterpret_cast<const float4*>(hr0 + q * 4);
    vd[0] = *reinterpret_cast<const float4*>(wdE + (size_t)bk0 * DIM + n0 + bn0v);
    vd[1] = *reinterpret_cast<const float4*>(wdE + (size_t)bk1 * DIM + n0 + bn1v);

    for (int kb = 0; kb < FDIM; kb += BK) {
#pragma unroll
        for (int q = 0; q < 4; q++) {
            As[ahalf + q * 4 + 0][arow] = f2tf32(av[q].x);
            As[ahalf + q * 4 + 1][arow] = f2tf32(av[q].y);
            As[ahalf + q * 4 + 2][arow] = f2tf32(av[q].z);
            As[ahalf + q * 4 + 3][arow] = f2tf32(av[q].w);
        }
        Bd[bk0][bn0v + 0] = f2tf32(vd[0].x); Bd[bk0][bn0v + 1] = f2tf32(vd[0].y);
        Bd[bk0][bn0v + 2] = f2tf32(vd[0].z); Bd[bk0][bn0v + 3] = f2tf32(vd[0].w);
        Bd[bk1][bn1v + 0] = f2tf32(vd[1].x); Bd[bk1][bn1v + 1] = f2tf32(vd[1].y);
        Bd[bk1][bn1v + 2] = f2tf32(vd[1].z); Bd[bk1][bn1v + 3] = f2tf32(vd[1].w);
        __syncthreads();

        int kn = kb + BK;
        if (kn < FDIM) {
#pragma unroll
            for (int q = 0; q < 4; q++)
                av[q] = *reinterpret_cast<const float4*>(hr0 + kn + q * 4);
            vd[0] = *reinterpret_cast<const float4*>(wdE + (size_t)(kn + bk0) * DIM + n0 + bn0v);
            vd[1] = *reinterpret_cast<const float4*>(wdE + (size_t)(kn + bk1) * DIM + n0 + bn1v);
        }

#pragma unroll
        for (int ks = 0; ks < BK / 8; ks++) {
            unsigned a[2][4];
#pragma unroll
            for (int mi = 0; mi < 2; mi++) {
                int r = wm + mi * 16;
                a[mi][0] = As[ks * 8 + tig    ][r + gid    ];
                a[mi][1] = As[ks * 8 + tig    ][r + gid + 8];
                a[mi][2] = As[ks * 8 + tig + 4][r + gid    ];
                a[mi][3] = As[ks * 8 + tig + 4][r + gid + 8];
            }
#pragma unroll
            for (int ni = 0; ni < 4; ni++) {
                int nc = wn + ni * 8 + gid;
                unsigned b[2] = { Bd[ks * 8 + tig][nc], Bd[ks * 8 + tig + 4][nc] };
#pragma unroll
                for (int mi = 0; mi < 2; mi++) {
                    mma_tf32(c[mi][ni], a[mi], b);
                }
            }
        }
        __syncthreads();
    }

    // epilogue: atomicAdd scatter (exactly 2 adds per out element -> deterministic)
#pragma unroll
    for (int mi = 0; mi < 2; mi++) {
#pragma unroll
        for (int half = 0; half < 2; half++) {
            int lm = wm + mi * 16 + gid + half * 8;
            int m  = m0 + lm;
            if (m >= cnt) continue;
            int tok = stok[lm];
            float* orow = out + (size_t)tok * DIM + n0;
#pragma unroll
            for (int ni = 0; ni < 4; ni++) {
                int col = wn + ni * 8 + 2 * tig;
                atomicAdd(&orow[col + 0], c[mi][ni][half * 2 + 0]);
                atomicAdd(&orow[col + 1], c[mi][ni][half * 2 + 1]);
            }
        }
    }
}

// ---------------------------------------------------------------------------
extern "C" void kernel_launch(void* const* d_in, const int* in_sizes, int n_in,
                              void* d_out, int out_size) {
    const float* x  = (const float*)d_in[0];   // [T, D]
    const float* gw = (const float*)d_in[1];   // [E, D]
    const float* wg = (const float*)d_in[2];   // [E, D, F]
    const float* wu = (const float*)d_in[3];   // [E, D, F]
    const float* wd = (const float*)d_in[4];   // [E, F, D]
    float* out = (float*)d_out;

    int n_out = T_TOK * DIM;
    zero_kernel<<<(n_out + 255) / 256, 256>>>(out, n_out);
    router_kernel<<<T_TOK, 128>>>(x, gw);

    dim3 g2(FDIM / BN, T_TOK / BM, NEXP);      // (22, 16, 8)
    gateup_mma<<<g2, 256>>>(x, wg, wu);

    dim3 g3(DIM / BN, T_TOK / BM, NEXP);       // (32, 16, 8)
    down_mma<<<g3, 256>>>(wd, out);
}

// round 4
// speedup vs baseline: 2.7281x; 1.2183x over previous
#include <cuda_runtime.h>
#include <math.h>

#define T_TOK 2048
#define DIM   2048
#define NEXP  8
#define FDIM  1408
#define STAGES 3

// ---- device scratch (no allocations allowed) ----
__device__ int   g_cnt[NEXP];
__device__ int   g_tok[NEXP][T_TOK];
__device__ float g_wt [NEXP][T_TOK];
__device__ float g_h  [NEXP * T_TOK * FDIM];   // SiLU(xWg)*(xWu)*w; rows >= cnt unused

// ---------------------------------------------------------------------------
__device__ __forceinline__ unsigned f2tf32(float x) {
    unsigned r; asm("cvt.rna.tf32.f32 %0, %1;" : "=r"(r) : "f"(x)); return r;
}
__device__ __forceinline__ void mma_tf32(float* c, const unsigned* a, const unsigned* b) {
    asm volatile(
        "mma.sync.aligned.m16n8k8.row.col.f32.tf32.tf32.f32 "
        "{%0,%1,%2,%3}, {%4,%5,%6,%7}, {%8,%9}, {%0,%1,%2,%3};\n"
        : "+f"(c[0]), "+f"(c[1]), "+f"(c[2]), "+f"(c[3])
        : "r"(a[0]), "r"(a[1]), "r"(a[2]), "r"(a[3]), "r"(b[0]), "r"(b[1]));
}
__device__ __forceinline__ void cp16(void* sdst, const void* gsrc) {
    unsigned s = (unsigned)__cvta_generic_to_shared(sdst);
    asm volatile("cp.async.cg.shared.global [%0], [%1], 16;\n" :: "r"(s), "l"(gsrc));
}
__device__ __forceinline__ void cp_commit() { asm volatile("cp.async.commit_group;\n"); }
template <int N>
__device__ __forceinline__ void cp_wait() { asm volatile("cp.async.wait_group %0;\n" :: "n"(N)); }

// ---------------------------------------------------------------------------
__global__ void zero_kernel(float* __restrict__ out, int n) {
    int i = blockIdx.x * blockDim.x + threadIdx.x;
    if (i < n) out[i] = 0.0f;
    if (blockIdx.x == 0 && threadIdx.x < NEXP) g_cnt[threadIdx.x] = 0;
}

// ---------------------------------------------------------------------------
// router: logits -> softmax -> top2 -> renorm -> scatter to expert lists
// ---------------------------------------------------------------------------
__global__ void router_kernel(const float* __restrict__ x,
                              const float* __restrict__ gw) {
    int t   = blockIdx.x;
    int tid = threadIdx.x;

    float p[NEXP];
#pragma unroll
    for (int e = 0; e < NEXP; e++) p[e] = 0.0f;

    const float* xr = x + (size_t)t * DIM;
    for (int d = tid; d < DIM; d += 128) {
        float xv = xr[d];
#pragma unroll
        for (int e = 0; e < NEXP; e++) p[e] += xv * gw[e * DIM + d];
    }

    __shared__ float sm[NEXP][128];
#pragma unroll
    for (int e = 0; e < NEXP; e++) sm[e][tid] = p[e];
    __syncthreads();

    for (int s = 64; s > 0; s >>= 1) {
        if (tid < s) {
#pragma unroll
            for (int e = 0; e < NEXP; e++) sm[e][tid] += sm[e][tid + s];
        }
        __syncthreads();
    }

    if (tid == 0) {
        float lg[NEXP];
        float mx = -1e30f;
#pragma unroll
        for (int e = 0; e < NEXP; e++) { lg[e] = sm[e][0]; mx = fmaxf(mx, lg[e]); }
        float pr[NEXP];
#pragma unroll
        for (int e = 0; e < NEXP; e++) pr[e] = expf(lg[e] - mx);
        int e0 = 0;
#pragma unroll
        for (int e = 1; e < NEXP; e++) if (pr[e] > pr[e0]) e0 = e;
        int e1 = (e0 == 0) ? 1 : 0;
#pragma unroll
        for (int e = 0; e < NEXP; e++)
            if (e != e0 && pr[e] > pr[e1]) e1 = e;
        float denom = pr[e0] + pr[e1];
        float w0 = pr[e0] / denom;
        float w1 = pr[e1] / denom;
        int p0 = atomicAdd(&g_cnt[e0], 1);
        g_tok[e0][p0] = t; g_wt[e0][p0] = w0;
        int p1 = atomicAdd(&g_cnt[e1], 1);
        g_tok[e1][p1] = t; g_wt[e1][p1] = w1;
    }
}

// ---------------------------------------------------------------------------
// gate+up GEMM: 128x64x16 tiles, cp.async 3-stage pipeline, 8 warps (4M x 2N)
// ---------------------------------------------------------------------------
#define GU_BM 128
#define GU_BN 64
#define GU_BK 16
#define GU_AW (GU_BK + 4)   // 20 floats, 80B rows
#define GU_BW (GU_BN + 8)   // 72 floats, 288B rows

__global__ void __launch_bounds__(256, 2)
gateup_mma(const float* __restrict__ x,
           const float* __restrict__ wg,
           const float* __restrict__ wu) {
    int e   = blockIdx.z;
    int cnt = g_cnt[e];
    int m0  = blockIdx.y * GU_BM;
    if (m0 >= cnt) return;
    int n0  = blockIdx.x * GU_BN;

    __shared__ float As[STAGES][GU_BM][GU_AW];
    __shared__ float Bg[STAGES][GU_BK][GU_BW];
    __shared__ float Bu[STAGES][GU_BK][GU_BW];
    __shared__ int   stok[GU_BM];
    __shared__ float swt[GU_BM];

    int tid = threadIdx.x;
    if (tid < GU_BM) {
        int m = m0 + tid;
        stok[tid] = (m < cnt) ? g_tok[e][m] : 0;
        swt[tid]  = (m < cnt) ? g_wt[e][m]  : 0.0f;
    }
    __syncthreads();

    const float* wgE = wg + (size_t)e * DIM * FDIM;
    const float* wuE = wu + (size_t)e * DIM * FDIM;

    int wid  = tid >> 5, lane = tid & 31;
    int gid  = lane >> 2, tig = lane & 3;
    int warpM = wid & 3, warpN = wid >> 2;       // 4 x 2 warps
    int wm = warpM * 32, wn = warpN * 32;

    // cp.async assignments
    int arow  = tid >> 1;           // A: 2 chunks/thread, row = tid/2
    int acol  = (tid & 1) * 8;      // float col of first chunk (8 floats = 2 chunks)
    int bk    = tid >> 4;           // B: 1 chunk/thread each for Bg, Bu
    int bn    = (tid & 15) * 4;

    const float* xr0 = x + (size_t)stok[arow] * DIM + acol;

    float cg[2][4][4] = {}, cu[2][4][4] = {};

    const int KT = DIM / GU_BK;     // 128

    // prologue: stage tiles 0 .. STAGES-2
#pragma unroll
    for (int s = 0; s < STAGES - 1; s++) {
        int kb = s * GU_BK;
        cp16(&As[s][arow][acol],     xr0 + kb);
        cp16(&As[s][arow][acol + 4], xr0 + kb + 4);
        cp16(&Bg[s][bk][bn], wgE + (size_t)(kb + bk) * FDIM + n0 + bn);
        cp16(&Bu[s][bk][bn], wuE + (size_t)(kb + bk) * FDIM + n0 + bn);
        cp_commit();
    }

    for (int kt = 0; kt < KT; kt++) {
        cp_wait<STAGES - 2>();
        __syncthreads();

        int ln = kt + STAGES - 1;
        if (ln < KT) {
            int s  = ln % STAGES;
            int kb = ln * GU_BK;
            cp16(&As[s][arow][acol],     xr0 + kb);
            cp16(&As[s][arow][acol + 4], xr0 + kb + 4);
            cp16(&Bg[s][bk][bn], wgE + (size_t)(kb + bk) * FDIM + n0 + bn);
            cp16(&Bu[s][bk][bn], wuE + (size_t)(kb + bk) * FDIM + n0 + bn);
        }
        cp_commit();

        int cs = kt % STAGES;
#pragma unroll
        for (int ks = 0; ks < GU_BK / 8; ks++) {
            int k0 = ks * 8;
            unsigned a[2][4];
#pragma unroll
            for (int mi = 0; mi < 2; mi++) {
                int r = wm + mi * 16 + gid;
                a[mi][0] = f2tf32(As[cs][r    ][k0 + tig    ]);
                a[mi][1] = f2tf32(As[cs][r + 8][k0 + tig    ]);
                a[mi][2] = f2tf32(As[cs][r    ][k0 + tig + 4]);
                a[mi][3] = f2tf32(As[cs][r + 8][k0 + tig + 4]);
            }
#pragma unroll
            for (int ni = 0; ni < 4; ni++) {
                int nc = wn + ni * 8 + gid;
                unsigned bgf[2] = { f2tf32(Bg[cs][k0 + tig][nc]), f2tf32(Bg[cs][k0 + tig + 4][nc]) };
                unsigned buf[2] = { f2tf32(Bu[cs][k0 + tig][nc]), f2tf32(Bu[cs][k0 + tig + 4][nc]) };
#pragma unroll
                for (int mi = 0; mi < 2; mi++) {
                    mma_tf32(cg[mi][ni], a[mi], bgf);
                    mma_tf32(cu[mi][ni], a[mi], buf);
                }
            }
        }
    }

    // epilogue: SiLU(g)*u*w -> g_h
#pragma unroll
    for (int mi = 0; mi < 2; mi++) {
#pragma unroll
        for (int half = 0; half < 2; half++) {
            int lm = wm + mi * 16 + gid + half * 8;
            int m  = m0 + lm;
            if (m >= cnt) continue;
            float w = swt[lm];
            float* hrow = g_h + ((size_t)e * T_TOK + m) * FDIM + n0;
#pragma unroll
            for (int ni = 0; ni < 4; ni++) {
                int col = wn + ni * 8 + 2 * tig;
                float g0 = cg[mi][ni][half * 2 + 0], g1 = cg[mi][ni][half * 2 + 1];
                float u0 = cu[mi][ni][half * 2 + 0], u1 = cu[mi][ni][half * 2 + 1];
                float2 hv;
                hv.x = (g0 / (1.0f + __expf(-g0))) * u0 * w;
                hv.y = (g1 / (1.0f + __expf(-g1))) * u1 * w;
                *reinterpret_cast<float2*>(hrow + col) = hv;
            }
        }
    }
}

// ---------------------------------------------------------------------------
// down GEMM + scatter-add: 128x128x16 tiles, cp.async 3-stage, warp tile 64x32
// ---------------------------------------------------------------------------
#define DN_BM 128
#define DN_BN 128
#define DN_BK 16
#define DN_AW (DN_BK + 4)    // 20 floats
#define DN_BW (DN_BN + 8)    // 136 floats, 544B rows

__global__ void __launch_bounds__(256, 2)
down_mma(const float* __restrict__ wd, float* __restrict__ out) {
    int e   = blockIdx.z;
    int cnt = g_cnt[e];
    int m0  = blockIdx.y * DN_BM;
    if (m0 >= cnt) return;
    int n0  = blockIdx.x * DN_BN;

    __shared__ float As[STAGES][DN_BM][DN_AW];
    __shared__ float Bd[STAGES][DN_BK][DN_BW];
    __shared__ int stok[DN_BM];

    int tid = threadIdx.x;
    if (tid < DN_BM) {
        int m = m0 + tid;
        stok[tid] = (m < cnt) ? g_tok[e][m] : 0;
    }
    __syncthreads();

    const float* wdE = wd + (size_t)e * FDIM * DIM;
    const float* hE  = g_h + (size_t)e * T_TOK * FDIM;

    int wid  = tid >> 5, lane = tid & 31;
    int gid  = lane >> 2, tig = lane & 3;
    int warpM = wid & 1, warpN = wid >> 1;       // 2 x 4 warps, warp tile 64x32
    int wm = warpM * 64, wn = warpN * 32;

    // cp.async assignments
    int arow = tid >> 1;            // A: 2 chunks/thread
    int acol = (tid & 1) * 8;
    int bidx = tid * 2;             // B: 2 chunks/thread, 512 chunks total
    int bk0  = bidx >> 5,  bn0c = (bidx & 31) * 4;
    int bk1  = (bidx + 1) >> 5, bn1c = ((bidx + 1) & 31) * 4;

    const float* hr0 = hE + (size_t)(m0 + arow) * FDIM + acol;

    float c[4][4][4] = {};

    const int KT = FDIM / DN_BK;    // 88

#pragma unroll
    for (int s = 0; s < STAGES - 1; s++) {
        int kb = s * DN_BK;
        cp16(&As[s][arow][acol],     hr0 + kb);
        cp16(&As[s][arow][acol + 4], hr0 + kb + 4);
        cp16(&Bd[s][bk0][bn0c], wdE + (size_t)(kb + bk0) * DIM + n0 + bn0c);
        cp16(&Bd[s][bk1][bn1c], wdE + (size_t)(kb + bk1) * DIM + n0 + bn1c);
        cp_commit();
    }

    for (int kt = 0; kt < KT; kt++) {
        cp_wait<STAGES - 2>();
        __syncthreads();

        int ln = kt + STAGES - 1;
        if (ln < KT) {
            int s  = ln % STAGES;
            int kb = ln * DN_BK;
            cp16(&As[s][arow][acol],     hr0 + kb);
            cp16(&As[s][arow][acol + 4], hr0 + kb + 4);
            cp16(&Bd[s][bk0][bn0c], wdE + (size_t)(kb + bk0) * DIM + n0 + bn0c);
            cp16(&Bd[s][bk1][bn1c], wdE + (size_t)(kb + bk1) * DIM + n0 + bn1c);
        }
        cp_commit();

        int cs = kt % STAGES;
#pragma unroll
        for (int ks = 0; ks < DN_BK / 8; ks++) {
            int k0 = ks * 8;
            unsigned a[4][4];
#pragma unroll
            for (int mi = 0; mi < 4; mi++) {
                int r = wm + mi * 16 + gid;
                a[mi][0] = f2tf32(As[cs][r    ][k0 + tig    ]);
                a[mi][1] = f2tf32(As[cs][r + 8][k0 + tig    ]);
                a[mi][2] = f2tf32(As[cs][r    ][k0 + tig + 4]);
                a[mi][3] = f2tf32(As[cs][r + 8][k0 + tig + 4]);
            }
#pragma unroll
            for (int ni = 0; ni < 4; ni++) {
                int nc = wn + ni * 8 + gid;
                unsigned b[2] = { f2tf32(Bd[cs][k0 + tig][nc]), f2tf32(Bd[cs][k0 + tig + 4][nc]) };
#pragma unroll
                for (int mi = 0; mi < 4; mi++) {
                    mma_tf32(c[mi][ni], a[mi], b);
                }
            }
        }
    }

    // epilogue: atomicAdd scatter (exactly 2 adds per out element -> deterministic)
#pragma unroll
    for (int mi = 0; mi < 4; mi++) {
#pragma unroll
        for (int half = 0; half < 2; half++) {
            int lm = wm + mi * 16 + gid + half * 8;
            int m  = m0 + lm;
            if (m >= cnt) continue;
            int tok = stok[lm];
            float* orow = out + (size_t)tok * DIM + n0;
#pragma unroll
            for (int ni = 0; ni < 4; ni++) {
                int col = wn + ni * 8 + 2 * tig;
                atomicAdd(&orow[col + 0], c[mi][ni][half * 2 + 0]);
                atomicAdd(&orow[col + 1], c[mi][ni][half * 2 + 1]);
            }
        }
    }
}

// ---------------------------------------------------------------------------
extern "C" void kernel_launch(void* const* d_in, const int* in_sizes, int n_in,
                              void* d_out, int out_size) {
    const float* x  = (const float*)d_in[0];   // [T, D]
    const float* gw = (const float*)d_in[1];   // [E, D]
    const float* wg = (const float*)d_in[2];   // [E, D, F]
    const float* wu = (const float*)d_in[3];   // [E, D, F]
    const float* wd = (const float*)d_in[4];   // [E, F, D]
    float* out = (float*)d_out;

    int n_out = T_TOK * DIM;
    zero_kernel<<<(n_out + 255) / 256, 256>>>(out, n_out);
    router_kernel<<<T_TOK, 128>>>(x, gw);

    dim3 g2(FDIM / GU_BN, T_TOK / GU_BM, NEXP);   // (22, 16, 8)
    gateup_mma<<<g2, 256>>>(x, wg, wu);

    dim3 g3(DIM / DN_BN, T_TOK / DN_BM, NEXP);    // (16, 16, 8)
    down_mma<<<g3, 256>>>(wd, out);
}

// round 6
// speedup vs baseline: 2.8876x; 1.0585x over previous
#include <cuda_runtime.h>
#include <math.h>

#define T_TOK 2048
#define DIM   2048
#define NEXP  8
#define FDIM  1408

// ---- device scratch (no allocations allowed) ----
__device__ int   g_cnt[NEXP];
__device__ int   g_tok[NEXP][T_TOK];
__device__ float g_wt [NEXP][T_TOK];
__device__ float g_h  [(size_t)NEXP * T_TOK * FDIM];   // SiLU(xWg)*(xWu)*w

// ---------------------------------------------------------------------------
__device__ __forceinline__ unsigned f2tf32(float x) {
    unsigned r; asm("cvt.rna.tf32.f32 %0, %1;" : "=r"(r) : "f"(x)); return r;
}
__device__ __forceinline__ void mma_tf32(float* c, const unsigned* a, const unsigned* b) {
    asm volatile(
        "mma.sync.aligned.m16n8k8.row.col.f32.tf32.tf32.f32 "
        "{%0,%1,%2,%3}, {%4,%5,%6,%7}, {%8,%9}, {%0,%1,%2,%3};\n"
        : "+f"(c[0]), "+f"(c[1]), "+f"(c[2]), "+f"(c[3])
        : "r"(a[0]), "r"(a[1]), "r"(a[2]), "r"(a[3]), "r"(b[0]), "r"(b[1]));
}
__device__ __forceinline__ void cp16(void* sdst, const void* gsrc) {
    unsigned s = (unsigned)__cvta_generic_to_shared(sdst);
    asm volatile("cp.async.cg.shared.global [%0], [%1], 16;\n" :: "r"(s), "l"(gsrc));
}
__device__ __forceinline__ void cp_commit() { asm volatile("cp.async.commit_group;\n"); }
__device__ __forceinline__ void cp_wait_all() { asm volatile("cp.async.wait_group 0;\n"); }

// ---------------------------------------------------------------------------
__global__ void zero_kernel(float* __restrict__ out, int n) {
    int i = blockIdx.x * blockDim.x + threadIdx.x;
    if (i < n) out[i] = 0.0f;
    if (blockIdx.x == 0 && threadIdx.x < NEXP) g_cnt[threadIdx.x] = 0;
}

// ---------------------------------------------------------------------------
// router: logits -> softmax -> top2 -> renorm -> scatter to expert lists
// ---------------------------------------------------------------------------
__global__ void router_kernel(const float* __restrict__ x,
                              const float* __restrict__ gw) {
    int t   = blockIdx.x;
    int tid = threadIdx.x;

    float p[NEXP];
#pragma unroll
    for (int e = 0; e < NEXP; e++) p[e] = 0.0f;

    const float* xr = x + (size_t)t * DIM;
    for (int d = tid; d < DIM; d += 128) {
        float xv = xr[d];
#pragma unroll
        for (int e = 0; e < NEXP; e++) p[e] += xv * gw[e * DIM + d];
    }

    __shared__ float sm[NEXP][128];
#pragma unroll
    for (int e = 0; e < NEXP; e++) sm[e][tid] = p[e];
    __syncthreads();

    for (int s = 64; s > 0; s >>= 1) {
        if (tid < s) {
#pragma unroll
            for (int e = 0; e < NEXP; e++) sm[e][tid] += sm[e][tid + s];
        }
        __syncthreads();
    }

    if (tid == 0) {
        float lg[NEXP];
        float mx = -1e30f;
#pragma unroll
        for (int e = 0; e < NEXP; e++) { lg[e] = sm[e][0]; mx = fmaxf(mx, lg[e]); }
        float pr[NEXP];
#pragma unroll
        for (int e = 0; e < NEXP; e++) pr[e] = expf(lg[e] - mx);
        int e0 = 0;
#pragma unroll
        for (int e = 1; e < NEXP; e++) if (pr[e] > pr[e0]) e0 = e;
        int e1 = (e0 == 0) ? 1 : 0;
#pragma unroll
        for (int e = 0; e < NEXP; e++)
            if (e != e0 && pr[e] > pr[e1]) e1 = e;
        float denom = pr[e0] + pr[e1];
        float w0 = pr[e0] / denom;
        float w1 = pr[e1] / denom;
        int p0 = atomicAdd(&g_cnt[e0], 1);
        g_tok[e0][p0] = t; g_wt[e0][p0] = w0;
        int p1 = atomicAdd(&g_cnt[e1], 1);
        g_tok[e1][p1] = t; g_wt[e1][p1] = w1;
    }
}

// ---------------------------------------------------------------------------
// gate+up GEMM: tile 128 x 128(per matrix) x 16, warp tile 64x32x2mat,
// 8 warps (2M x 4N), 2-stage cp.async
// ---------------------------------------------------------------------------
#define GU_BM 128
#define GU_BN 128
#define GU_BK 16
#define GU_AW (GU_BK + 4)    // 20 floats / 80B rows
#define GU_BW (GU_BN + 8)    // 136 floats / 544B rows

__global__ void __launch_bounds__(256, 1)
gateup_mma(const float* __restrict__ x,
           const float* __restrict__ wg,
           const float* __restrict__ wu) {
    int e   = blockIdx.z;
    int cnt = g_cnt[e];
    int m0  = blockIdx.y * GU_BM;
    if (m0 >= cnt) return;
    int n0  = blockIdx.x * GU_BN;

    __shared__ float As[2][GU_BM][GU_AW];
    __shared__ float Bg[2][GU_BK][GU_BW];
    __shared__ float Bu[2][GU_BK][GU_BW];
    __shared__ int   stok[GU_BM];
    __shared__ float swt[GU_BM];

    int tid = threadIdx.x;
    if (tid < GU_BM) {
        int m = m0 + tid;
        stok[tid] = (m < cnt) ? g_tok[e][m] : 0;
        swt[tid]  = (m < cnt) ? g_wt[e][m]  : 0.0f;
    }
    __syncthreads();

    const float* wgE = wg + (size_t)e * DIM * FDIM;
    const float* wuE = wu + (size_t)e * DIM * FDIM;

    int wid  = tid >> 5, lane = tid & 31;
    int gid  = lane >> 2, tig = lane & 3;
    int warpM = wid & 1, warpN = wid >> 1;       // 2 x 4 warps
    int wm = warpM * 64, wn = warpN * 32;

    // cp.async assignments
    int arow = tid >> 1;            // A: 2 chunks/thread
    int acol = (tid & 1) * 8;
    int bk   = tid >> 5;            // B: 2 chunks/thread/matrix (k = bk, bk+8)
    int bn   = (tid & 31) * 4;

    const float* xr0 = x + (size_t)stok[arow] * DIM + acol;

    float cg[4][4][4] = {}, cu[4][4][4] = {};

    const int KT = DIM / GU_BK;     // 128

    // prologue: stage 0
    {
        cp16(&As[0][arow][acol],     xr0);
        cp16(&As[0][arow][acol + 4], xr0 + 4);
#pragma unroll
        for (int q = 0; q < 2; q++) {
            int k = bk + q * 8;
            cp16(&Bg[0][k][bn], wgE + (size_t)k * FDIM + n0 + bn);
            cp16(&Bu[0][k][bn], wuE + (size_t)k * FDIM + n0 + bn);
        }
        cp_commit();
    }

    for (int kt = 0; kt < KT; kt++) {
        cp_wait_all();
        __syncthreads();

        int ln = kt + 1;
        if (ln < KT) {
            int s  = ln & 1;
            int kb = ln * GU_BK;
            cp16(&As[s][arow][acol],     xr0 + kb);
            cp16(&As[s][arow][acol + 4], xr0 + kb + 4);
#pragma unroll
            for (int q = 0; q < 2; q++) {
                int k = bk + q * 8;
                cp16(&Bg[s][k][bn], wgE + (size_t)(kb + k) * FDIM + n0 + bn);
                cp16(&Bu[s][k][bn], wuE + (size_t)(kb + k) * FDIM + n0 + bn);
            }
            cp_commit();
        }

        int cs = kt & 1;
#pragma unroll
        for (int ks = 0; ks < GU_BK / 8; ks++) {
            int k0 = ks * 8;
            unsigned a[4][4];
#pragma unroll
            for (int mi = 0; mi < 4; mi++) {
                int r = wm + mi * 16 + gid;
                a[mi][0] = f2tf32(As[cs][r    ][k0 + tig    ]);
                a[mi][1] = f2tf32(As[cs][r + 8][k0 + tig    ]);
                a[mi][2] = f2tf32(As[cs][r    ][k0 + tig + 4]);
                a[mi][3] = f2tf32(As[cs][r + 8][k0 + tig + 4]);
            }
#pragma unroll
            for (int ni = 0; ni < 4; ni++) {
                int nc = wn + ni * 8 + gid;
                unsigned bg2[2] = { f2tf32(Bg[cs][k0 + tig][nc]), f2tf32(Bg[cs][k0 + tig + 4][nc]) };
                unsigned bu2[2] = { f2tf32(Bu[cs][k0 + tig][nc]), f2tf32(Bu[cs][k0 + tig + 4][nc]) };
#pragma unroll
                for (int mi = 0; mi < 4; mi++) {
                    mma_tf32(cg[mi][ni], a[mi], bg2);
                    mma_tf32(cu[mi][ni], a[mi], bu2);
                }
            }
        }
    }

    // epilogue: SiLU(g)*u*w -> g_h
#pragma unroll
    for (int mi = 0; mi < 4; mi++) {
#pragma unroll
        for (int half = 0; half < 2; half++) {
            int lm = wm + mi * 16 + gid + half * 8;
            int m  = m0 + lm;
            if (m >= cnt) continue;
            float w = swt[lm];
            float* hrow = g_h + ((size_t)e * T_TOK + m) * FDIM + n0;
#pragma unroll
            for (int ni = 0; ni < 4; ni++) {
                int col = wn + ni * 8 + 2 * tig;
                float g0 = cg[mi][ni][half * 2 + 0], g1 = cg[mi][ni][half * 2 + 1];
                float u0 = cu[mi][ni][half * 2 + 0], u1 = cu[mi][ni][half * 2 + 1];
                float2 hv;
                hv.x = (g0 / (1.0f + __expf(-g0))) * u0 * w;
                hv.y = (g1 / (1.0f + __expf(-g1))) * u1 * w;
                *reinterpret_cast<float2*>(hrow + col) = hv;
            }
        }
    }
}

// ---------------------------------------------------------------------------
// down GEMM + scatter-add: tile 128 x 256 x 16, warp tile 64x64,
// 8 warps (2M x 4N), 2-stage cp.async
// ---------------------------------------------------------------------------
#define DN_BM 128
#define DN_BN 256
#define DN_BK 16
#define DN_AW (DN_BK + 4)    // 20 floats
#define DN_BW (DN_BN + 8)    // 264 floats / 1056B rows

__global__ void __launch_bounds__(256, 1)
down_mma(const float* __restrict__ wd, float* __restrict__ out) {
    int e   = blockIdx.z;
    int cnt = g_cnt[e];
    int m0  = blockIdx.y * DN_BM;
    if (m0 >= cnt) return;
    int n0  = blockIdx.x * DN_BN;

    __shared__ float As[2][DN_BM][DN_AW];
    __shared__ float Bd[2][DN_BK][DN_BW];
    __shared__ int stok[DN_BM];

    int tid = threadIdx.x;
    if (tid < DN_BM) {
        int m = m0 + tid;
        stok[tid] = (m < cnt) ? g_tok[e][m] : 0;
    }
    __syncthreads();

    const float* wdE = wd + (size_t)e * FDIM * DIM;
    const float* hE  = g_h + (size_t)e * T_TOK * FDIM;

    int wid  = tid >> 5, lane = tid & 31;
    int gid  = lane >> 2, tig = lane & 3;
    int warpM = wid & 1, warpN = wid >> 1;       // 2 x 4 warps, warp tile 64x64
    int wm = warpM * 64, wn = warpN * 64;

    // cp.async assignments
    int arow = tid >> 1;            // A: 2 chunks/thread
    int acol = (tid & 1) * 8;
    int bk   = tid >> 6;            // B: 4 chunks/thread (k = bk + q*4)
    int bn   = (tid & 63) * 4;

    const float* hr0 = hE + (size_t)(m0 + arow) * FDIM + acol;

    float c[4][8][4] = {};

    const int KT = FDIM / DN_BK;    // 88

    // prologue: stage 0
    {
        cp16(&As[0][arow][acol],     hr0);
        cp16(&As[0][arow][acol + 4], hr0 + 4);
#pragma unroll
        for (int q = 0; q < 4; q++) {
            int k = bk + q * 4;
            cp16(&Bd[0][k][bn], wdE + (size_t)k * DIM + n0 + bn);
        }
        cp_commit();
    }

    for (int kt = 0; kt < KT; kt++) {
        cp_wait_all();
        __syncthreads();

        int ln = kt + 1;
        if (ln < KT) {
            int s  = ln & 1;
            int kb = ln * DN_BK;
            cp16(&As[s][arow][acol],     hr0 + kb);
            cp16(&As[s][arow][acol + 4], hr0 + kb + 4);
#pragma unroll
            for (int q = 0; q < 4; q++) {
                int k = bk + q * 4;
                cp16(&Bd[s][k][bn], wdE + (size_t)(kb + k) * DIM + n0 + bn);
            }
            cp_commit();
        }

        int cs = kt & 1;
#pragma unroll
        for (int ks = 0; ks < DN_BK / 8; ks++) {
            int k0 = ks * 8;
            unsigned a[4][4];
#pragma unroll
            for (int mi = 0; mi < 4; mi++) {
                int r = wm + mi * 16 + gid;
                a[mi][0] = f2tf32(As[cs][r    ][k0 + tig    ]);
                a[mi][1] = f2tf32(As[cs][r + 8][k0 + tig    ]);
                a[mi][2] = f2tf32(As[cs][r    ][k0 + tig + 4]);
                a[mi][3] = f2tf32(As[cs][r + 8][k0 + tig + 4]);
            }
#pragma unroll
            for (int ni = 0; ni < 8; ni++) {
                int nc = wn + ni * 8 + gid;
                unsigned b[2] = { f2tf32(Bd[cs][k0 + tig][nc]), f2tf32(Bd[cs][k0 + tig + 4][nc]) };
#pragma unroll
                for (int mi = 0; mi < 4; mi++) {
                    mma_tf32(c[mi][ni], a[mi], b);
                }
            }
        }
    }

    // epilogue: atomicAdd scatter (exactly 2 adds per out element -> deterministic)
#pragma unroll
    for (int mi = 0; mi < 4; mi++) {
#pragma unroll
        for (int half = 0; half < 2; half++) {
            int lm = wm + mi * 16 + gid + half * 8;
            int m  = m0 + lm;
            if (m >= cnt) continue;
            int tok = stok[lm];
            float* orow = out + (size_t)tok * DIM + n0;
#pragma unroll
            for (int ni = 0; ni < 8; ni++) {
                int col = wn + ni * 8 + 2 * tig;
                atomicAdd(&orow[col + 0], c[mi][ni][half * 2 + 0]);
                atomicAdd(&orow[col + 1], c[mi][ni][half * 2 + 1]);
            }
        }
    }
}

// ---------------------------------------------------------------------------
extern "C" void kernel_launch(void* const* d_in, const int* in_sizes, int n_in,
                              void* d_out, int out_size) {
    const float* x  = (const float*)d_in[0];   // [T, D]
    const float* gw = (const float*)d_in[1];   // [E, D]
    const float* wg = (const float*)d_in[2];   // [E, D, F]
    const float* wu = (const float*)d_in[3];   // [E, D, F]
    const float* wd = (const float*)d_in[4];   // [E, F, D]
    float* out = (float*)d_out;

    int n_out = T_TOK * DIM;
    zero_kernel<<<(n_out + 255) / 256, 256>>>(out, n_out);
    router_kernel<<<T_TOK, 128>>>(x, gw);

    dim3 g2(FDIM / GU_BN, T_TOK / GU_BM, NEXP);   // (11, 16, 8)
    gateup_mma<<<g2, 256>>>(x, wg, wu);

    dim3 g3(DIM / DN_BN, T_TOK / DN_BM, NEXP);    // (8, 16, 8)
    down_mma<<<g3, 256>>>(wd, out);
}